// round 4
// baseline (speedup 1.0000x reference)
#include <cuda_runtime.h>

#define ZDIM 8
#define EDIM 32
#define HDIM 64
#define NEG 0.01f
#define LEN 510
#define NTOT 32640            /* 64 * 510 */
#define HALF 16320            /* NTOT/2 */
#define LOG_OFF (NTOT*ZDIM)   /* 261120 */
#define CTA 128

typedef unsigned long long u64;

// per-(z,n) log|dout| scratch (deterministic, no fp atomics)
__device__ float g_dlog[ZDIM * NTOT];

__device__ __forceinline__ u64 pk2(float lo, float hi){
    u64 r; asm("mov.b64 %0, {%1, %2};" : "=l"(r) : "f"(lo), "f"(hi)); return r;
}
__device__ __forceinline__ void up2(u64 v, float& lo, float& hi){
    asm("mov.b64 {%0, %1}, %2;" : "=f"(lo), "=f"(hi) : "l"(v));
}
__device__ __forceinline__ u64 fma2(u64 a, u64 b, u64 c){
    u64 d; asm("fma.rn.f32x2 %0, %1, %2, %3;" : "=l"(d) : "l"(a), "l"(b), "l"(c));
    return d;
}
__device__ __forceinline__ float leaky(float p){
    return fmaxf(p, 0.f) + NEG * fminf(p, 0.f);
}

__global__ __launch_bounds__(CTA)
void mlp_jvp_kernel(const float* __restrict__ x,
                    const float* __restrict__ emb,
                    const float* __restrict__ W1,
                    const float* __restrict__ b1,
                    const float* __restrict__ W2,
                    const float* __restrict__ b2,
                    const float* __restrict__ W3,
                    const float* __restrict__ b3,
                    float* __restrict__ out)
{
    // plain (non-duplicated) weights: ~25.3 KB -> 2 CTAs/SM
    __shared__ __align__(16) float sW1[(EDIM+1)*HDIM];  // [e][h], e=32 row = d(pre1)/dxt
    __shared__ __align__(16) float sW2[HDIM*HDIM];      // [i][j]
    __shared__ __align__(8)  float sB1[HDIM];
    __shared__ __align__(8)  float sB2[HDIM];
    __shared__ float sW3[HDIM];
    __shared__ float sB3v;

    const int tid = threadIdx.x;
    const int z   = blockIdx.y;

    {   // stage this z's weights
        const float* g1 = W1 + z*(EDIM+1)*HDIM;
        for (int i = tid; i < (EDIM+1)*HDIM; i += CTA) sW1[i] = g1[i];
        const float* g2 = W2 + z*HDIM*HDIM;
        for (int i = tid; i < HDIM*HDIM; i += CTA) sW2[i] = g2[i];
        if (tid < HDIM){
            sB1[tid] = b1[z*HDIM + tid];
            sB2[tid] = b2[z*HDIM + tid];
            sW3[tid] = W3[z*HDIM + tid];
        }
        if (tid == 0) sB3v = b3[z];
    }
    __syncthreads();

    const int m = blockIdx.x * CTA + tid;
    if (m >= HALF) return;

    // two rows per thread: m and m + HALF (same z)
    const int b0 = m / LEN,  t0 = m  - b0*LEN,  s0 = b0*512 + t0 + 2;
    const int n1 = m + HALF;
    const int b1i= n1 / LEN, t1 = n1 - b1i*LEN, s1 = b1i*512 + t1 + 2;
    const float* e0 = emb + (size_t)s0 * EDIM;
    const float* e1 = emb + (size_t)s1 * EDIM;
    const float xt0 = x[s0*ZDIM + z];
    const float xt1 = x[s1*ZDIM + z];

    // ---------------- layer 1: pre1 pairs over adjacent h, both rows ----------------
    u64 A0[HDIM/2], A1[HDIM/2];
    #pragma unroll
    for (int p = 0; p < HDIM/2; p++){
        u64 bb = *reinterpret_cast<const u64*>(sB1 + 2*p);
        A0[p] = bb; A1[p] = bb;
    }
    #pragma unroll 1
    for (int e = 0; e < EDIM; e++){
        float v0 = __ldg(e0 + e), v1 = __ldg(e1 + e);
        u64 d0 = pk2(v0, v0), d1 = pk2(v1, v1);
        const ulonglong2* wr = reinterpret_cast<const ulonglong2*>(sW1 + e*HDIM);
        #pragma unroll
        for (int q = 0; q < 16; q++){
            ulonglong2 w = wr[q];                  // one LDS.128 = 2 h-pairs, shared by both rows
            A0[2*q]   = fma2(d0, w.x, A0[2*q]);
            A0[2*q+1] = fma2(d0, w.y, A0[2*q+1]);
            A1[2*q]   = fma2(d1, w.x, A1[2*q]);
            A1[2*q+1] = fma2(d1, w.y, A1[2*q+1]);
        }
    }
    {   // x_t coordinate (input index 32)
        u64 d0 = pk2(xt0, xt0), d1 = pk2(xt1, xt1);
        const ulonglong2* wr = reinterpret_cast<const ulonglong2*>(sW1 + EDIM*HDIM);
        #pragma unroll
        for (int q = 0; q < 16; q++){
            ulonglong2 w = wr[q];
            A0[2*q]   = fma2(d0, w.x, A0[2*q]);
            A0[2*q+1] = fma2(d0, w.y, A0[2*q+1]);
            A1[2*q]   = fma2(d1, w.x, A1[2*q]);
            A1[2*q+1] = fma2(d1, w.y, A1[2*q+1]);
        }
    }

    // ---------------- activation: hp[i] = {h_row0_i, h_row1_i} ----------------
    u64 hp[HDIM];
    #pragma unroll
    for (int p = 0; p < HDIM/2; p++){
        float p00, p01; up2(A0[p], p00, p01);
        float p10, p11; up2(A1[p], p10, p11);
        hp[2*p]   = pk2(leaky(p00), leaky(p10));
        hp[2*p+1] = pk2(leaky(p01), leaky(p11));
    }

    // ---------------- layer 2 (+ fused layer 3): 4 j-tiles of 16 ----------------
    float o0 = sB3v, o1 = sB3v, dc0 = 0.f, dc1 = 0.f;
    const float* cw = sW1 + EDIM*HDIM;             // d(pre1_i)/dxt = W1[32][i]
    #pragma unroll 1
    for (int jb = 0; jb < HDIM; jb += 16){
        u64 cf0[8], ct0[8], cf1[8], ct1[8];        // 8 j-pairs x {fwd,tang} x {row0,row1}
        #pragma unroll
        for (int p = 0; p < 8; p++){
            u64 bb = *reinterpret_cast<const u64*>(sB2 + jb + 2*p);
            cf0[p] = bb; cf1[p] = bb; ct0[p] = 0ull; ct1[p] = 0ull;
        }
        #pragma unroll
        for (int i = 0; i < HDIM; i++){
            float h0, h1; up2(hp[i], h0, h1);
            u64 hd0 = pk2(h0, h0), hd1 = pk2(h1, h1);
            float ci = cw[i];
            float cn = NEG * ci;
            float d0v = (h0 >= 0.f) ? ci : cn;     // dh_i = leaky'(pre1_i) * W1[32][i]
            float d1v = (h1 >= 0.f) ? ci : cn;
            u64 dd0 = pk2(d0v, d0v), dd1 = pk2(d1v, d1v);
            const ulonglong2* wr = reinterpret_cast<const ulonglong2*>(sW2 + i*HDIM + jb);
            #pragma unroll
            for (int q = 0; q < 4; q++){
                ulonglong2 w = wr[q];              // one LDS.128 serves 4 streams below
                cf0[2*q]   = fma2(hd0, w.x, cf0[2*q]);
                cf0[2*q+1] = fma2(hd0, w.y, cf0[2*q+1]);
                cf1[2*q]   = fma2(hd1, w.x, cf1[2*q]);
                cf1[2*q+1] = fma2(hd1, w.y, cf1[2*q+1]);
                ct0[2*q]   = fma2(dd0, w.x, ct0[2*q]);
                ct0[2*q+1] = fma2(dd0, w.y, ct0[2*q+1]);
                ct1[2*q]   = fma2(dd1, w.x, ct1[2*q]);
                ct1[2*q+1] = fma2(dd1, w.y, ct1[2*q+1]);
            }
        }
        // tile epilogue: leaky(pre2) -> layer 3 dot
        #pragma unroll
        for (int p = 0; p < 8; p++){
            float w3a = sW3[jb + 2*p], w3b = sW3[jb + 2*p + 1];
            float pa, pb, da, db, sa, sb;
            up2(cf0[p], pa, pb); up2(ct0[p], da, db);
            sa = (pa >= 0.f) ? 1.f : NEG;  sb = (pb >= 0.f) ? 1.f : NEG;
            o0  = fmaf(sa*pa, w3a, o0);    o0  = fmaf(sb*pb, w3b, o0);
            dc0 = fmaf(sa*da, w3a, dc0);   dc0 = fmaf(sb*db, w3b, dc0);
            up2(cf1[p], pa, pb); up2(ct1[p], da, db);
            sa = (pa >= 0.f) ? 1.f : NEG;  sb = (pb >= 0.f) ? 1.f : NEG;
            o1  = fmaf(sa*pa, w3a, o1);    o1  = fmaf(sb*pb, w3b, o1);
            dc1 = fmaf(sa*da, w3a, dc1);   dc1 = fmaf(sb*db, w3b, dc1);
        }
    }

    out[(size_t)m  * ZDIM + z] = o0;               // residuals[b,t,z]
    out[(size_t)n1 * ZDIM + z] = o1;
    g_dlog[z*NTOT + m]  = __logf(fabsf(dc0));
    g_dlog[z*NTOT + n1] = __logf(fabsf(dc1));
}

__global__ void logdet_reduce(float* __restrict__ out){
    int n = blockIdx.x * blockDim.x + threadIdx.x;
    if (n >= NTOT) return;
    float s = 0.f;
    #pragma unroll
    for (int zz = 0; zz < ZDIM; zz++) s += g_dlog[zz * NTOT + n];
    out[LOG_OFF + n] = s;                          // log_abs_det[b,t]
}

extern "C" void kernel_launch(void* const* d_in, const int* in_sizes, int n_in,
                              void* d_out, int out_size){
    const float* x    = (const float*)d_in[0];
    const float* embv = (const float*)d_in[1];
    const float* W1   = (const float*)d_in[2];
    const float* b1   = (const float*)d_in[3];
    const float* W2   = (const float*)d_in[4];
    const float* b2   = (const float*)d_in[5];
    const float* W3   = (const float*)d_in[6];
    const float* b3   = (const float*)d_in[7];
    float* out = (float*)d_out;

    dim3 grid((HALF + CTA - 1) / CTA, ZDIM);       // 128 x 8 CTAs
    mlp_jvp_kernel<<<grid, CTA>>>(x, embv, W1, b1, W2, b2, W3, b3, out);
    logdet_reduce<<<(NTOT + 255)/256, 256>>>(out);
}

// round 5
// speedup vs baseline: 1.4195x; 1.4195x over previous
#include <cuda_runtime.h>

#define ZDIM 8
#define EDIM 32
#define HDIM 64
#define NEG 0.01f
#define LEN 510
#define NTOT 32640            /* 64 * 510 = 255 * 128 */
#define LOG_OFF (NTOT*ZDIM)   /* 261120 */
#define CTA 128

typedef unsigned long long u64;

// per-(z,n) log|dout| scratch (deterministic, no fp atomics)
__device__ float g_dlog[ZDIM * NTOT];

__device__ __forceinline__ u64 pk2(float lo, float hi){
    u64 r; asm("mov.b64 %0, {%1, %2};" : "=l"(r) : "f"(lo), "f"(hi)); return r;
}
__device__ __forceinline__ void up2(u64 v, float& lo, float& hi){
    asm("mov.b64 {%0, %1}, %2;" : "=f"(lo), "=f"(hi) : "l"(v));
}
__device__ __forceinline__ u64 fma2(u64 a, u64 b, u64 c){
    u64 d; asm("fma.rn.f32x2 %0, %1, %2, %3;" : "=l"(d) : "l"(a), "l"(b), "l"(c));
    return d;
}
__device__ __forceinline__ float leaky(float p){
    return fmaxf(p, 0.f) + NEG * fminf(p, 0.f);
}

__global__ __launch_bounds__(CTA, 3)
void mlp_jvp_kernel(const float* __restrict__ x,
                    const float* __restrict__ emb,
                    const float* __restrict__ W1,
                    const float* __restrict__ b1,
                    const float* __restrict__ W2,
                    const float* __restrict__ b2,
                    const float* __restrict__ W3,
                    const float* __restrict__ b3,
                    float* __restrict__ out)
{
    // ~26 KB static smem; 3 CTAs/SM
    __shared__ __align__(16) float sW1[(EDIM+1)*HDIM];  // [e][h]; row e=32 = d(pre1)/dxt
    __shared__ __align__(16) float sW2[HDIM*HDIM];      // [i][j]
    __shared__ __align__(16) float sCwN[HDIM];          // NEG * W1[32][i]
    __shared__ __align__(8)  float sB1[HDIM];
    __shared__ __align__(8)  float sB2[HDIM];
    __shared__ float sW3[HDIM];
    __shared__ float sB3v;

    const int tid = threadIdx.x;
    const int z   = blockIdx.y;

    {   // stage this z's weights
        const float* g1 = W1 + z*(EDIM+1)*HDIM;
        for (int i = tid; i < (EDIM+1)*HDIM; i += CTA) sW1[i] = g1[i];
        const float* g2 = W2 + z*HDIM*HDIM;
        for (int i = tid; i < HDIM*HDIM; i += CTA) sW2[i] = g2[i];
        if (tid < HDIM){
            sB1[tid]  = b1[z*HDIM + tid];
            sB2[tid]  = b2[z*HDIM + tid];
            sW3[tid]  = W3[z*HDIM + tid];
            sCwN[tid] = NEG * g1[EDIM*HDIM + tid];
        }
        if (tid == 0) sB3v = b3[z];
    }
    __syncthreads();

    const int n   = blockIdx.x * CTA + tid;      // exact: 255*128 = NTOT
    const int bb  = n / LEN;
    const int tt  = n - bb * LEN;
    const int src = bb * 512 + tt + 2;           // LL=512, LAGS=2
    const float4* e4 = reinterpret_cast<const float4*>(emb + (size_t)src * EDIM);
    const float xt = x[src * ZDIM + z];

    // ---------------- layer 1: pre1 in adjacent-h pairs ----------------
    u64 A[HDIM/2];
    #pragma unroll
    for (int p = 0; p < HDIM/2; p++)
        A[p] = *reinterpret_cast<const u64*>(sB1 + 2*p);

    #pragma unroll 2
    for (int g = 0; g < 8; g++){                 // 8 float4 = 32 emb coords
        float4 v = __ldg(e4 + g);
        #pragma unroll
        for (int s = 0; s < 4; s++){
            float a = (s==0)?v.x:(s==1)?v.y:(s==2)?v.z:v.w;
            u64 ad = pk2(a, a);
            const ulonglong2* wr = reinterpret_cast<const ulonglong2*>(sW1 + (4*g+s)*HDIM);
            #pragma unroll
            for (int q = 0; q < 16; q++){
                ulonglong2 w = wr[q];
                A[2*q]   = fma2(ad, w.x, A[2*q]);
                A[2*q+1] = fma2(ad, w.y, A[2*q+1]);
            }
        }
    }
    {   // x_t coordinate (input index 32)
        u64 ad = pk2(xt, xt);
        const ulonglong2* wr = reinterpret_cast<const ulonglong2*>(sW1 + EDIM*HDIM);
        #pragma unroll
        for (int q = 0; q < 16; q++){
            ulonglong2 w = wr[q];
            A[2*q]   = fma2(ad, w.x, A[2*q]);
            A[2*q+1] = fma2(ad, w.y, A[2*q+1]);
        }
    }

    // ---------------- activation: h as 64 scalars (A dies here) ----------------
    float h[HDIM];
    #pragma unroll
    for (int p = 0; p < HDIM/2; p++){
        float p0, p1; up2(A[p], p0, p1);
        h[2*p]   = leaky(p0);
        h[2*p+1] = leaky(p1);
    }

    // ---------------- layer 2 (+ fused layer 3): 2 j-tiles of 32 ----------------
    const float* cw = sW1 + EDIM*HDIM;           // d(pre1_i)/dxt
    float oacc = sB3v, dacc = 0.f;
    #pragma unroll 1
    for (int jb = 0; jb < HDIM; jb += 32){
        u64 af[16], at[16];                      // fwd / tangent, pair-over-j
        #pragma unroll
        for (int p = 0; p < 16; p++){
            af[p] = *reinterpret_cast<const u64*>(sB2 + jb + 2*p);
            at[p] = 0ull;
        }
        #pragma unroll 16
        for (int i = 0; i < HDIM; i++){
            float hi = h[i];
            float ds = (hi >= 0.f) ? cw[i] : sCwN[i];  // dh_i (sign(h)==sign(pre1))
            u64 hd = pk2(hi, hi);
            u64 dd = pk2(ds, ds);
            const ulonglong2* wr = reinterpret_cast<const ulonglong2*>(sW2 + i*HDIM + jb);
            #pragma unroll
            for (int q = 0; q < 8; q++){
                ulonglong2 w = wr[q];            // 4 j per load, feeds 8 MACs
                af[2*q]   = fma2(hd, w.x, af[2*q]);
                af[2*q+1] = fma2(hd, w.y, af[2*q+1]);
                at[2*q]   = fma2(dd, w.x, at[2*q]);
                at[2*q+1] = fma2(dd, w.y, at[2*q+1]);
            }
        }
        // tile epilogue: leaky(pre2) -> layer-3 dot (fwd + tangent)
        #pragma unroll
        for (int p = 0; p < 16; p++){
            float pa, pb, da, db;
            up2(af[p], pa, pb); up2(at[p], da, db);
            float w3a = sW3[jb + 2*p], w3b = sW3[jb + 2*p + 1];
            float sa = (pa >= 0.f) ? 1.f : NEG;
            float sb = (pb >= 0.f) ? 1.f : NEG;
            oacc = fmaf(sa*pa, w3a, oacc);  oacc = fmaf(sb*pb, w3b, oacc);
            dacc = fmaf(sa*da, w3a, dacc);  dacc = fmaf(sb*db, w3b, dacc);
        }
    }

    out[(size_t)n * ZDIM + z] = oacc;            // residuals[b,t,z]
    g_dlog[z*NTOT + n] = __logf(fabsf(dacc));
}

__global__ void logdet_reduce(float* __restrict__ out){
    int n = blockIdx.x * blockDim.x + threadIdx.x;
    if (n >= NTOT) return;
    float s = 0.f;
    #pragma unroll
    for (int zz = 0; zz < ZDIM; zz++) s += g_dlog[zz * NTOT + n];
    out[LOG_OFF + n] = s;                        // log_abs_det[b,t]
}

extern "C" void kernel_launch(void* const* d_in, const int* in_sizes, int n_in,
                              void* d_out, int out_size){
    const float* x    = (const float*)d_in[0];
    const float* embv = (const float*)d_in[1];
    const float* W1   = (const float*)d_in[2];
    const float* b1   = (const float*)d_in[3];
    const float* W2   = (const float*)d_in[4];
    const float* b2   = (const float*)d_in[5];
    const float* W3   = (const float*)d_in[6];
    const float* b3   = (const float*)d_in[7];
    float* out = (float*)d_out;

    dim3 grid(NTOT / CTA, ZDIM);                 // 255 x 8 CTAs, no tail
    mlp_jvp_kernel<<<grid, CTA>>>(x, embv, W1, b1, W2, b2, W3, b3, out);
    logdet_reduce<<<(NTOT + 255)/256, 256>>>(out);
}